// round 10
// baseline (speedup 1.0000x reference)
#include <cuda_runtime.h>
#include <cuda_fp16.h>
#include <cstdint>

// Problem dims (fixed)
#define Bq   8
#define Tq   2048
#define Cq   1024
#define HIDq 4096
#define Mq   (Bq*Tq)        // 16384 rows
#define NCH  32             // WKV chunks
#define LCH  (Tq/NCH)       // 64 steps per chunk

// GEMM tiling: CTA 128x128 (256 thr), warp 64x32, BK=64 fp16 (128B rows)
#define BM     128
#define BN     128
#define BKK    64
#define STAGES 3
#define ASTGB  (BM*128)              // 16384 bytes per A stage
#define BSTGB  (BN*128)              // 16384 bytes per B stage
#define STGB   (ASTGB + BSTGB)       // 32768 per stage
#define GEMM_SMEM (STAGES*STGB + 1024)   // 99328 -> 2 CTAs/SM

// ---------------- scratch (static device globals; no allocation) ----------
__device__ __half g_xk[(size_t)Mq*Cq];
__device__ __half g_xv[(size_t)Mq*Cq];
__device__ __half g_xr[(size_t)Mq*Cq];
__device__ __half g_fk[(size_t)Mq*Cq];
__device__ __half g_fr[(size_t)Mq*Cq];
__device__ __half g_rw[(size_t)Mq*Cq];
__device__ __half g_kk[(size_t)Mq*HIDq];
__device__ float  g_k [(size_t)Mq*Cq];
__device__ float  g_v [(size_t)Mq*Cq];
__device__ float  g_sr[(size_t)Mq*Cq];
__device__ float  g_x1[(size_t)Mq*Cq];
__device__ float  g_sg[(size_t)Mq*Cq];
__device__ float  g_Ca[(size_t)NCH*Bq*Cq];
__device__ float  g_Cb[(size_t)NCH*Bq*Cq];
__device__ float  g_Sa[(size_t)NCH*Bq*Cq];
__device__ float  g_Sb[(size_t)NCH*Bq*Cq];
// half weights: Wk,Wv,Wr,Wo,Fr (C*C each) then Fk,Fv (HID*C each)
__device__ __half g_wh[(size_t)5*Cq*Cq + (size_t)2*HIDq*Cq];

// ---------------- helpers --------------------------------------------------
__device__ __forceinline__ void mma_f16(float* c, const uint32_t* a, const uint32_t* b) {
    asm volatile(
        "mma.sync.aligned.m16n8k16.row.col.f32.f16.f16.f32 "
        "{%0,%1,%2,%3}, {%4,%5,%6,%7}, {%8,%9}, {%0,%1,%2,%3};"
        : "+f"(c[0]), "+f"(c[1]), "+f"(c[2]), "+f"(c[3])
        : "r"(a[0]), "r"(a[1]), "r"(a[2]), "r"(a[3]), "r"(b[0]), "r"(b[1]));
}
__device__ __forceinline__ void ldsm_x4(uint32_t* d, uint32_t addr) {
    asm volatile("ldmatrix.sync.aligned.m8n8.x4.shared.b16 {%0,%1,%2,%3}, [%4];"
        : "=r"(d[0]), "=r"(d[1]), "=r"(d[2]), "=r"(d[3]) : "r"(addr));
}

__device__ __forceinline__ uint32_t smem_u32(const void* p) {
    uint32_t a;
    asm("{ .reg .u64 t; cvta.to.shared.u64 t, %1; cvt.u32.u64 %0, t; }" : "=r"(a) : "l"(p));
    return a;
}
__device__ __forceinline__ void cp16(uint32_t dst, const void* src) {
    asm volatile("cp.async.cg.shared.global [%0], [%1], 16;" :: "r"(dst), "l"(src));
}
__device__ __forceinline__ void cp_commit() { asm volatile("cp.async.commit_group;"); }
template<int N> __device__ __forceinline__ void cp_wait() {
    asm volatile("cp.async.wait_group %0;" :: "n"(N));
}

// block-wide reduce of 4 values (256 threads)
__device__ __forceinline__ void bred4(float& a, float& b, float& c, float& d) {
    #pragma unroll
    for (int o = 16; o; o >>= 1) {
        a += __shfl_xor_sync(0xffffffffu, a, o);
        b += __shfl_xor_sync(0xffffffffu, b, o);
        c += __shfl_xor_sync(0xffffffffu, c, o);
        d += __shfl_xor_sync(0xffffffffu, d, o);
    }
    __shared__ float sm[8][4];
    int w = threadIdx.x >> 5, l = threadIdx.x & 31;
    if (l == 0) { sm[w][0] = a; sm[w][1] = b; sm[w][2] = c; sm[w][3] = d; }
    __syncthreads();
    a = b = c = d = 0.f;
    #pragma unroll
    for (int j = 0; j < 8; j++) { a += sm[j][0]; b += sm[j][1]; c += sm[j][2]; d += sm[j][3]; }
}

// ---------------- weight conversion fp32 -> fp16 ---------------------------
__global__ __launch_bounds__(256) void w2h5(
    const float* __restrict__ w0, const float* __restrict__ w1, const float* __restrict__ w2,
    const float* __restrict__ w3, const float* __restrict__ w4, __half* __restrict__ dst)
{
    const size_t CC = (size_t)Cq * Cq;
    const float* src = (blockIdx.y == 0) ? w0 : (blockIdx.y == 1) ? w1 :
                       (blockIdx.y == 2) ? w2 : (blockIdx.y == 3) ? w3 : w4;
    __half* d = dst + (size_t)blockIdx.y * CC;
    const int i = blockIdx.x * blockDim.x + threadIdx.x;   // < CC/4
    float4 v = reinterpret_cast<const float4*>(src)[i];
    __half2 h01 = __floats2half2_rn(v.x, v.y);
    __half2 h23 = __floats2half2_rn(v.z, v.w);
    uint2 u; u.x = *reinterpret_cast<uint32_t*>(&h01); u.y = *reinterpret_cast<uint32_t*>(&h23);
    reinterpret_cast<uint2*>(d)[i] = u;
}

__global__ __launch_bounds__(256) void w2h2(
    const float* __restrict__ w0, const float* __restrict__ w1, __half* __restrict__ dst)
{
    const size_t HC = (size_t)HIDq * Cq;
    const float* src = (blockIdx.y == 0) ? w0 : w1;
    __half* d = dst + (size_t)blockIdx.y * HC;
    const int i = blockIdx.x * blockDim.x + threadIdx.x;   // < HC/4
    float4 v = reinterpret_cast<const float4*>(src)[i];
    __half2 h01 = __floats2half2_rn(v.x, v.y);
    __half2 h23 = __floats2half2_rn(v.z, v.w);
    uint2 u; u.x = *reinterpret_cast<uint32_t*>(&h01); u.y = *reinterpret_cast<uint32_t*>(&h23);
    reinterpret_cast<uint2*>(d)[i] = u;
}

// ---------------- fused LayerNorm + time-shift + token-mix (half out) ------
template<int NOUT>
__global__ __launch_bounds__(256) void ln_mix(
    const float* __restrict__ x, const float* __restrict__ g, const float* __restrict__ be,
    const float* __restrict__ m0, const float* __restrict__ m1, const float* __restrict__ m2,
    __half* __restrict__ o0, __half* __restrict__ o1, __half* __restrict__ o2)
{
    const int row = blockIdx.x;          // b*T + t
    const int t   = row & (Tq - 1);
    const int i   = threadIdx.x;         // one float4 per thread (C/4 = 256)

    const float4 v = reinterpret_cast<const float4*>(x + (size_t)row * Cq)[i];
    float4 u = make_float4(0.f, 0.f, 0.f, 0.f);
    if (t > 0) u = reinterpret_cast<const float4*>(x + (size_t)(row - 1) * Cq)[i];

    float s  = v.x + v.y + v.z + v.w;
    float ss = v.x*v.x + v.y*v.y + v.z*v.z + v.w*v.w;
    float sp = u.x + u.y + u.z + u.w;
    float sq = u.x*u.x + u.y*u.y + u.z*u.z + u.w*u.w;
    bred4(s, ss, sp, sq);

    const float inv = 1.f / (float)Cq;
    const float mC = s * inv;
    const float rs = rsqrtf(ss * inv - mC * mC + 1e-5f);
    const float mP = sp * inv;
    const float rp = rsqrtf(sq * inv - mP * mP + 1e-5f);

    const float4 g4 = reinterpret_cast<const float4*>(g)[i];
    const float4 b4 = reinterpret_cast<const float4*>(be)[i];

    float xa[4], xx[4];
    const float* vv = &v.x; const float* uu = &u.x;
    const float* gg = &g4.x; const float* bb = &b4.x;
    #pragma unroll
    for (int j = 0; j < 4; j++) {
        xa[j] = (vv[j] - mC) * rs * gg[j] + bb[j];
        xx[j] = (t > 0) ? ((uu[j] - mP) * rp * gg[j] + bb[j]) : 0.f;
    }

    const size_t oi = (size_t)row * (Cq / 4) + i;
    {
        const float4 w4 = reinterpret_cast<const float4*>(m0)[i];
        const float* ww = &w4.x; float r[4];
        #pragma unroll
        for (int j = 0; j < 4; j++) r[j] = xa[j] * ww[j] + xx[j] * (1.f - ww[j]);
        __half2 h01 = __floats2half2_rn(r[0], r[1]);
        __half2 h23 = __floats2half2_rn(r[2], r[3]);
        uint2 o; o.x = *reinterpret_cast<uint32_t*>(&h01); o.y = *reinterpret_cast<uint32_t*>(&h23);
        reinterpret_cast<uint2*>(o0)[oi] = o;
    }
    {
        const float4 w4 = reinterpret_cast<const float4*>(m1)[i];
        const float* ww = &w4.x; float r[4];
        #pragma unroll
        for (int j = 0; j < 4; j++) r[j] = xa[j] * ww[j] + xx[j] * (1.f - ww[j]);
        __half2 h01 = __floats2half2_rn(r[0], r[1]);
        __half2 h23 = __floats2half2_rn(r[2], r[3]);
        uint2 o; o.x = *reinterpret_cast<uint32_t*>(&h01); o.y = *reinterpret_cast<uint32_t*>(&h23);
        reinterpret_cast<uint2*>(o1)[oi] = o;
    }
    if (NOUT == 3) {
        const float4 w4 = reinterpret_cast<const float4*>(m2)[i];
        const float* ww = &w4.x; float r[4];
        #pragma unroll
        for (int j = 0; j < 4; j++) r[j] = xa[j] * ww[j] + xx[j] * (1.f - ww[j]);
        __half2 h01 = __floats2half2_rn(r[0], r[1]);
        __half2 h23 = __floats2half2_rn(r[2], r[3]);
        uint2 o; o.x = *reinterpret_cast<uint32_t*>(&h01); o.y = *reinterpret_cast<uint32_t*>(&h23);
        reinterpret_cast<uint2*>(o2)[oi] = o;
    }
}

// ---------------- fp16 GEMM core, 128x128 tile, 8 warps @ 64x32, ldmatrix --
// 256 threads/CTA, ~120 regs/thread -> 2 CTAs/SM = 16 warps/SM.
// 3-stage cp.async ring, prefetch distance 1, ONE __syncthreads per tile.
// EPI: 0 none(f32) | 1 sigmoid(f32) | 2 relu^2 -> HALF out | 3 aux1+acc | 4 aux1+aux2*acc

__device__ __forceinline__ void fill_tile(uint32_t sbase, int stage,
    const __half* __restrict__ Ag, const __half* __restrict__ Wg, int K, int k0, int tid)
{
    const uint32_t sa = sbase + (uint32_t)stage * STGB;
    #pragma unroll
    for (int p = 0; p < 4; p++) {            // A: 128 rows x 8 chunks = 1024
        const int id  = tid + p * 256;
        const int row = id >> 3, c = id & 7;
        const uint32_t off = (uint32_t)(row * 128 + c * 16);
        cp16(sa + (off ^ ((off >> 3) & 0x70)), Ag + (size_t)row * K + k0 + c * 8);
    }
    const uint32_t sb = sa + ASTGB;
    #pragma unroll
    for (int p = 0; p < 4; p++) {            // B: 128 rows x 8 chunks = 1024
        const int id  = tid + p * 256;
        const int row = id >> 3, c = id & 7;
        const uint32_t off = (uint32_t)(row * 128 + c * 16);
        cp16(sb + (off ^ ((off >> 3) & 0x70)), Wg + (size_t)row * K + k0 + c * 8);
    }
}

template<int EPI>
__device__ __forceinline__ void epi_store(void* __restrict__ out, size_t idx,
    float c0, float c1, const float* __restrict__ a1, const float* __restrict__ a2)
{
    if (EPI == 2) {
        c0 = fmaxf(c0, 0.f); c0 *= c0;
        c1 = fmaxf(c1, 0.f); c1 *= c1;
        __half2 h = __floats2half2_rn(c0, c1);
        *reinterpret_cast<__half2*>((__half*)out + idx) = h;
        return;
    }
    if (EPI == 1) { c0 = 1.f / (1.f + __expf(-c0)); c1 = 1.f / (1.f + __expf(-c1)); }
    else if (EPI == 3) { c0 += a1[idx]; c1 += a1[idx + 1]; }
    else if (EPI == 4) { c0 = a1[idx] + a2[idx] * c0; c1 = a1[idx + 1] + a2[idx + 1] * c1; }
    float2 t; t.x = c0; t.y = c1;
    *reinterpret_cast<float2*>((float*)out + idx) = t;
}

template<int EPI>
__device__ __forceinline__ void gemm_body(
    const __half* __restrict__ A, const __half* __restrict__ W, void* __restrict__ out,
    const float* __restrict__ aux1, const float* __restrict__ aux2, int N, int K,
    uint32_t sbase)
{
    const int tid  = threadIdx.x;
    const int lane = tid & 31;
    const int warp = tid >> 5;    // 0..7
    const int wm   = warp >> 2;   // 0..1 -> 64 rows each
    const int wn   = warp & 3;    // 0..3 -> 32 cols each

    const int brow = blockIdx.y * BM;
    const int bcol = blockIdx.x * BN;
    const __half* Ag = A + (size_t)brow * K;
    const __half* Wg = W + (size_t)bcol * K;
    const int ntiles = K / BKK;

    // ldmatrix lane mapping (verified round-8 algebra)
    const int g = lane >> 3, r = lane & 7;
    const uint32_t colA = (uint32_t)((g >> 1) * 16);
    const uint32_t colB = (uint32_t)((g & 1) * 16);
    uint32_t arow128[4], axor[4];
    #pragma unroll
    for (int mt = 0; mt < 4; mt++) {
        const int row = wm * 64 + mt * 16 + (g & 1) * 8 + r;
        arow128[mt] = (uint32_t)(row * 128);
        axor[mt]    = (uint32_t)((row & 7) * 16);
    }
    uint32_t brow128[2], bxor[2];
    #pragma unroll
    for (int p = 0; p < 2; p++) {
        const int row = wn * 32 + p * 16 + (g >> 1) * 8 + r;
        brow128[p] = (uint32_t)(row * 128);
        bxor[p]    = (uint32_t)((row & 7) * 16);
    }

    // prologue: 1 tile in flight (prefetch distance 1)
    fill_tile(sbase, 0, Ag, Wg, K, 0, tid); cp_commit();

    float acc[4][4][4];
    #pragma unroll
    for (int mt = 0; mt < 4; mt++)
        #pragma unroll
        for (int nt = 0; nt < 4; nt++)
            #pragma unroll
            for (int q = 0; q < 4; q++) acc[mt][nt][q] = 0.f;

    for (int t = 0; t < ntiles; t++) {
        const int tp = t + 1;
        if (tp < ntiles) fill_tile(sbase, tp % STAGES, Ag, Wg, K, tp * BKK, tid);
        cp_commit();                       // unconditional (empty group on last iter)
        cp_wait<1>();                      // stage t complete
        __syncthreads();                   // the ONLY barrier per tile

        const uint32_t sA = sbase + (uint32_t)(t % STAGES) * STGB;
        const uint32_t sB = sA + ASTGB;

        #pragma unroll
        for (int ks = 0; ks < 4; ks++) {
            const uint32_t cb = (uint32_t)(ks * 32);
            uint32_t a[4][4], b[2][4];
            #pragma unroll
            for (int mt = 0; mt < 4; mt++)
                ldsm_x4(a[mt], sA + arow128[mt] + ((colA + cb) ^ axor[mt]));
            #pragma unroll
            for (int p = 0; p < 2; p++)
                ldsm_x4(b[p], sB + brow128[p] + ((colB + cb) ^ bxor[p]));
            #pragma unroll
            for (int mt = 0; mt < 4; mt++)
                #pragma unroll
                for (int nt = 0; nt < 4; nt++)
                    mma_f16(acc[mt][nt], a[mt], &b[nt >> 1][(nt & 1) * 2]);
        }
    }

    // epilogue straight from registers
    const int qrow = lane >> 2, qcol = lane & 3;
    #pragma unroll
    for (int mt = 0; mt < 4; mt++) {
        #pragma unroll
        for (int nt = 0; nt < 4; nt++) {
            const int row = brow + wm * 64 + mt * 16 + qrow;
            const int col = bcol + wn * 32 + nt * 8 + qcol * 2;
            const size_t i0 = (size_t)row * N + col;
            const size_t i1 = (size_t)(row + 8) * N + col;
            epi_store<EPI>(out, i0, acc[mt][nt][0], acc[mt][nt][1], aux1, aux2);
            epi_store<EPI>(out, i1, acc[mt][nt][2], acc[mt][nt][3], aux1, aux2);
        }
    }
}

template<int EPI>
__global__ __launch_bounds__(256, 2) void gemm_f16(
    const __half* __restrict__ A, const __half* __restrict__ W, void* __restrict__ out,
    const float* __restrict__ aux1, const float* __restrict__ aux2, int N, int K)
{
    extern __shared__ float dsm[];
    const uint32_t sbase = (smem_u32(dsm) + 1023u) & ~1023u;
    gemm_body<EPI>(A, W, out, aux1, aux2, N, K, sbase);
}

// merged k & v GEMMs (same EPI=0): z selects operand set; 2x wave depth -> less tail
__global__ __launch_bounds__(256, 2) void gemm_kv(
    const __half* __restrict__ xk, const __half* __restrict__ xv,
    const __half* __restrict__ wk, const __half* __restrict__ wv,
    float* __restrict__ k, float* __restrict__ v, int N, int K)
{
    extern __shared__ float dsm[];
    const uint32_t sbase = (smem_u32(dsm) + 1023u) & ~1023u;
    const bool z = (blockIdx.z != 0);
    gemm_body<0>(z ? xv : xk, z ? wv : wk, z ? (void*)v : (void*)k,
                 nullptr, nullptr, N, K, sbase);
}

// ---------------- WKV chunked scan ------------------------------------------
__global__ __launch_bounds__(256) void wkv_phase_a(
    const float* __restrict__ k, const float* __restrict__ v,
    const float* __restrict__ td, float* __restrict__ Ca, float* __restrict__ Cb)
{
    const int gid = blockIdx.x * blockDim.x + threadIdx.x;   // < NCH*B*C
    const int c  = gid & (Cq - 1);
    const int r  = gid >> 10;
    const int b  = r & (Bq - 1);
    const int ch = r >> 3;
    const float w  = -expf(td[c]);
    const float dw = expf(w);
    const size_t base = ((size_t)(b * Tq + ch * LCH)) * Cq + c;
    float sa = 0.f, sb = 0.f;
    #pragma unroll 4
    for (int i = 0; i < LCH; i++) {
        const float kt = k[base + (size_t)i * Cq];
        const float vt = v[base + (size_t)i * Cq];
        const float ek = __expf(kt);
        sa = fmaf(dw, sa, ek * vt);
        sb = fmaf(dw, sb, ek);
    }
    Ca[gid] = sa; Cb[gid] = sb;
}

__global__ __launch_bounds__(256) void wkv_scan(
    const float* __restrict__ td,
    const float* __restrict__ Ca, const float* __restrict__ Cb,
    float* __restrict__ Sa, float* __restrict__ Sb)
{
    const int sid = blockIdx.x * blockDim.x + threadIdx.x;   // < B*C
    const int c = sid & (Cq - 1);
    const float w  = -expf(td[c]);
    const float dL = expf((float)LCH * w);
    float sa = 0.f, sb = 0.f;
    #pragma unroll
    for (int ch = 0; ch < NCH; ch++) {
        const int idx = ch * (Bq * Cq) + sid;
        Sa[idx] = sa; Sb[idx] = sb;
        sa = fmaf(dL, sa, Ca[idx]);
        sb = fmaf(dL, sb, Cb[idx]);
    }
}

__global__ __launch_bounds__(256) void wkv_phase_b(
    const float* __restrict__ k, const float* __restrict__ v, const float* __restrict__ sr,
    const float* __restrict__ td, const float* __restrict__ tf,
    const float* __restrict__ Sa, const float* __restrict__ Sb, __half* __restrict__ out)
{
    const int gid = blockIdx.x * blockDim.x + threadIdx.x;
    const int c  = gid & (Cq - 1);
    const int r  = gid >> 10;
    const int b  = r & (Bq - 1);
    const int ch = r >> 3;
    const float w  = -expf(td[c]);
    const float dw = expf(w);
    const float eu = expf(tf[c]);
    float a = Sa[gid], bb = Sb[gid];
    const size_t base = ((size_t)(b * Tq + ch * LCH)) * Cq + c;
    #pragma unroll 4
    for (int i = 0; i < LCH; i++) {
        const size_t off = base + (size_t)i * Cq;
        const float kt = k[off];
        const float vt = v[off];
        const float ek = __expf(kt);
        const float euk = eu * ek;
        const float y = (a + euk * vt) / (bb + euk);
        out[off] = __float2half_rn(sr[off] * y);   // feeds Wo GEMM only
        a  = fmaf(dw, a,  ek * vt);
        bb = fmaf(dw, bb, ek);
    }
}

// ---------------- launch -----------------------------------------------------
extern "C" void kernel_launch(void* const* d_in, const int* in_sizes, int n_in,
                              void* d_out, int out_size)
{
    const float* x     = (const float*)d_in[0];
    const float* ln1_g = (const float*)d_in[1];
    const float* ln1_b = (const float*)d_in[2];
    const float* ln2_g = (const float*)d_in[3];
    const float* ln2_b = (const float*)d_in[4];
    const float* td    = (const float*)d_in[5];
    const float* tf    = (const float*)d_in[6];
    const float* tmk   = (const float*)d_in[7];
    const float* tmv   = (const float*)d_in[8];
    const float* tmr   = (const float*)d_in[9];
    const float* Wk    = (const float*)d_in[10];
    const float* Wv    = (const float*)d_in[11];
    const float* Wr    = (const float*)d_in[12];
    const float* Wo    = (const float*)d_in[13];
    const float* fmk   = (const float*)d_in[14];
    const float* fmr   = (const float*)d_in[15];
    const float* Fk    = (const float*)d_in[16];
    const float* Fr    = (const float*)d_in[17];
    const float* Fv    = (const float*)d_in[18];
    float* out = (float*)d_out;

    __half *xk, *xv, *xr, *fk, *fr, *rw, *kk, *wh;
    float *k, *v, *sr, *x1, *sg, *Ca, *Cb, *Sa, *Sb;
    cudaGetSymbolAddress((void**)&xk, g_xk);
    cudaGetSymbolAddress((void**)&xv, g_xv);
    cudaGetSymbolAddress((void**)&xr, g_xr);
    cudaGetSymbolAddress((void**)&fk, g_fk);
    cudaGetSymbolAddress((void**)&fr, g_fr);
    cudaGetSymbolAddress((void**)&rw, g_rw);
    cudaGetSymbolAddress((void**)&kk, g_kk);
    cudaGetSymbolAddress((void**)&wh, g_wh);
    cudaGetSymbolAddress((void**)&k,  g_k);
    cudaGetSymbolAddress((void**)&v,  g_v);
    cudaGetSymbolAddress((void**)&sr, g_sr);
    cudaGetSymbolAddress((void**)&x1, g_x1);
    cudaGetSymbolAddress((void**)&sg, g_sg);
    cudaGetSymbolAddress((void**)&Ca, g_Ca);
    cudaGetSymbolAddress((void**)&Cb, g_Cb);
    cudaGetSymbolAddress((void**)&Sa, g_Sa);
    cudaGetSymbolAddress((void**)&Sb, g_Sb);

    const size_t CC = (size_t)Cq * Cq;          // 1M
    const size_t HC = (size_t)HIDq * Cq;        // 4M
    __half* hWk = wh;
    __half* hWv = wh + CC;
    __half* hWr = wh + 2 * CC;
    __half* hWo = wh + 3 * CC;
    __half* hFr = wh + 4 * CC;
    __half* hFk = wh + 5 * CC;
    __half* hFv = wh + 5 * CC + HC;

    cudaFuncSetAttribute(gemm_f16<0>, cudaFuncAttributeMaxDynamicSharedMemorySize, GEMM_SMEM);
    cudaFuncSetAttribute(gemm_f16<1>, cudaFuncAttributeMaxDynamicSharedMemorySize, GEMM_SMEM);
    cudaFuncSetAttribute(gemm_f16<2>, cudaFuncAttributeMaxDynamicSharedMemorySize, GEMM_SMEM);
    cudaFuncSetAttribute(gemm_f16<3>, cudaFuncAttributeMaxDynamicSharedMemorySize, GEMM_SMEM);
    cudaFuncSetAttribute(gemm_f16<4>, cudaFuncAttributeMaxDynamicSharedMemorySize, GEMM_SMEM);
    cudaFuncSetAttribute(gemm_kv,     cudaFuncAttributeMaxDynamicSharedMemorySize, GEMM_SMEM);

    // 0,1: weight conversion
    w2h5<<<dim3((unsigned)(CC / 4 / 256), 5), 256>>>(Wk, Wv, Wr, Wo, Fr, wh);
    w2h2<<<dim3((unsigned)(HC / 4 / 256), 2), 256>>>(Fk, Fv, wh + 5 * CC);

    const dim3 gC (Cq / BN,  Mq / BM);       // (8, 128)      N=1024
    const dim3 gC2(Cq / BN,  Mq / BM, 2);    // (8, 128, 2)   k+v merged
    const dim3 gH (HIDq / BN, Mq / BM);      // (32, 128)     N=4096

    // att branch
    ln_mix<3><<<Mq, 256>>>(x, ln1_g, ln1_b, tmk, tmv, tmr, xk, xv, xr);        // 2
    gemm_kv<<<gC2, 256, GEMM_SMEM>>>(xk, xv, hWk, hWv, k, v, Cq, Cq);          // 3
    gemm_f16<1><<<gC, 256, GEMM_SMEM>>>(xr, hWr, sr, nullptr, nullptr, Cq, Cq); // 4

    wkv_phase_a<<<(NCH * Bq * Cq) / 256, 256>>>(k, v, td, Ca, Cb);             // 5
    wkv_scan   <<<(Bq * Cq) / 256, 256>>>(td, Ca, Cb, Sa, Sb);
    wkv_phase_b<<<(NCH * Bq * Cq) / 256, 256>>>(k, v, sr, td, tf, Sa, Sb, rw);

    gemm_f16<3><<<gC, 256, GEMM_SMEM>>>(rw, hWo, x1, x, nullptr, Cq, Cq);

    // ffn branch
    ln_mix<2><<<Mq, 256>>>(x1, ln2_g, ln2_b, fmk, fmr, nullptr, fk, fr, nullptr);
    gemm_f16<2><<<gH, 256, GEMM_SMEM>>>(fk, hFk, kk, nullptr, nullptr, HIDq, Cq);
    gemm_f16<1><<<gC, 256, GEMM_SMEM>>>(fr, hFr, sg, nullptr, nullptr, Cq, Cq);
    gemm_f16<4><<<gC, 256, GEMM_SMEM>>>(kk, hFv, out, x1, sg, Cq, HIDq);
}

// round 11
// speedup vs baseline: 1.0406x; 1.0406x over previous
#include <cuda_runtime.h>
#include <cuda_fp16.h>
#include <cstdint>

// Problem dims (fixed)
#define Bq   8
#define Tq   2048
#define Cq   1024
#define HIDq 4096
#define Mq   (Bq*Tq)        // 16384 rows
#define NCH  32             // WKV chunks
#define LCH  (Tq/NCH)       // 64 steps per chunk

// GEMM tiling: CTA 128x128 (128 thr), warp 64x64, BK=64 fp16 (128B rows)
#define BM     128
#define BN     128
#define BKK    64
#define STAGES 3
#define ASTGB  (BM*128)              // 16384 bytes per A stage
#define BSTGB  (BN*128)              // 16384 bytes per B stage
#define STGB   (ASTGB + BSTGB)       // 32768 per stage
#define GEMM_SMEM (STAGES*STGB + 1024)   // 99328 -> 2 CTAs/SM

// ---------------- scratch (static device globals; no allocation) ----------
__device__ __half g_xk[(size_t)Mq*Cq];
__device__ __half g_xv[(size_t)Mq*Cq];
__device__ __half g_xr[(size_t)Mq*Cq];
__device__ __half g_fk[(size_t)Mq*Cq];
__device__ __half g_fr[(size_t)Mq*Cq];
__device__ __half g_rw[(size_t)Mq*Cq];
__device__ __half g_kk[(size_t)Mq*HIDq];
__device__ float  g_k [(size_t)Mq*Cq];
__device__ float  g_v [(size_t)Mq*Cq];
__device__ float  g_sr[(size_t)Mq*Cq];
__device__ float  g_x1[(size_t)Mq*Cq];
__device__ float  g_sg[(size_t)Mq*Cq];
__device__ float  g_Ca[(size_t)NCH*Bq*Cq];
__device__ float  g_Cb[(size_t)NCH*Bq*Cq];
__device__ float  g_Sa[(size_t)NCH*Bq*Cq];
__device__ float  g_Sb[(size_t)NCH*Bq*Cq];
// half weights: Wk,Wv,Wr,Wo,Fr (C*C each) then Fk,Fv (HID*C each)
__device__ __half g_wh[(size_t)5*Cq*Cq + (size_t)2*HIDq*Cq];

// ---------------- helpers --------------------------------------------------
__device__ __forceinline__ void mma_f16(float* c, const uint32_t* a, const uint32_t* b) {
    asm volatile(
        "mma.sync.aligned.m16n8k16.row.col.f32.f16.f16.f32 "
        "{%0,%1,%2,%3}, {%4,%5,%6,%7}, {%8,%9}, {%0,%1,%2,%3};"
        : "+f"(c[0]), "+f"(c[1]), "+f"(c[2]), "+f"(c[3])
        : "r"(a[0]), "r"(a[1]), "r"(a[2]), "r"(a[3]), "r"(b[0]), "r"(b[1]));
}
__device__ __forceinline__ void ldsm_x4(uint32_t* d, uint32_t addr) {
    asm volatile("ldmatrix.sync.aligned.m8n8.x4.shared.b16 {%0,%1,%2,%3}, [%4];"
        : "=r"(d[0]), "=r"(d[1]), "=r"(d[2]), "=r"(d[3]) : "r"(addr));
}

__device__ __forceinline__ uint32_t smem_u32(const void* p) {
    uint32_t a;
    asm("{ .reg .u64 t; cvta.to.shared.u64 t, %1; cvt.u32.u64 %0, t; }" : "=r"(a) : "l"(p));
    return a;
}
__device__ __forceinline__ void cp16(uint32_t dst, const void* src) {
    asm volatile("cp.async.cg.shared.global [%0], [%1], 16;" :: "r"(dst), "l"(src));
}
__device__ __forceinline__ void cp_commit() { asm volatile("cp.async.commit_group;"); }
template<int N> __device__ __forceinline__ void cp_wait() {
    asm volatile("cp.async.wait_group %0;" :: "n"(N));
}

// block-wide reduce of 4 values (256 threads)
__device__ __forceinline__ void bred4(float& a, float& b, float& c, float& d) {
    #pragma unroll
    for (int o = 16; o; o >>= 1) {
        a += __shfl_xor_sync(0xffffffffu, a, o);
        b += __shfl_xor_sync(0xffffffffu, b, o);
        c += __shfl_xor_sync(0xffffffffu, c, o);
        d += __shfl_xor_sync(0xffffffffu, d, o);
    }
    __shared__ float sm[8][4];
    int w = threadIdx.x >> 5, l = threadIdx.x & 31;
    if (l == 0) { sm[w][0] = a; sm[w][1] = b; sm[w][2] = c; sm[w][3] = d; }
    __syncthreads();
    a = b = c = d = 0.f;
    #pragma unroll
    for (int j = 0; j < 8; j++) { a += sm[j][0]; b += sm[j][1]; c += sm[j][2]; d += sm[j][3]; }
}

// ---------------- weight conversion fp32 -> fp16 ---------------------------
__global__ __launch_bounds__(256) void w2h5(
    const float* __restrict__ w0, const float* __restrict__ w1, const float* __restrict__ w2,
    const float* __restrict__ w3, const float* __restrict__ w4, __half* __restrict__ dst)
{
    const size_t CC = (size_t)Cq * Cq;
    const float* src = (blockIdx.y == 0) ? w0 : (blockIdx.y == 1) ? w1 :
                       (blockIdx.y == 2) ? w2 : (blockIdx.y == 3) ? w3 : w4;
    __half* d = dst + (size_t)blockIdx.y * CC;
    const int i = blockIdx.x * blockDim.x + threadIdx.x;   // < CC/4
    float4 v = reinterpret_cast<const float4*>(src)[i];
    __half2 h01 = __floats2half2_rn(v.x, v.y);
    __half2 h23 = __floats2half2_rn(v.z, v.w);
    uint2 u; u.x = *reinterpret_cast<uint32_t*>(&h01); u.y = *reinterpret_cast<uint32_t*>(&h23);
    reinterpret_cast<uint2*>(d)[i] = u;
}

__global__ __launch_bounds__(256) void w2h2(
    const float* __restrict__ w0, const float* __restrict__ w1, __half* __restrict__ dst)
{
    const size_t HC = (size_t)HIDq * Cq;
    const float* src = (blockIdx.y == 0) ? w0 : w1;
    __half* d = dst + (size_t)blockIdx.y * HC;
    const int i = blockIdx.x * blockDim.x + threadIdx.x;   // < HC/4
    float4 v = reinterpret_cast<const float4*>(src)[i];
    __half2 h01 = __floats2half2_rn(v.x, v.y);
    __half2 h23 = __floats2half2_rn(v.z, v.w);
    uint2 u; u.x = *reinterpret_cast<uint32_t*>(&h01); u.y = *reinterpret_cast<uint32_t*>(&h23);
    reinterpret_cast<uint2*>(d)[i] = u;
}

// ---------------- fused LayerNorm + time-shift + token-mix (half out) ------
template<int NOUT>
__global__ __launch_bounds__(256) void ln_mix(
    const float* __restrict__ x, const float* __restrict__ g, const float* __restrict__ be,
    const float* __restrict__ m0, const float* __restrict__ m1, const float* __restrict__ m2,
    __half* __restrict__ o0, __half* __restrict__ o1, __half* __restrict__ o2)
{
    const int row = blockIdx.x;          // b*T + t
    const int t   = row & (Tq - 1);
    const int i   = threadIdx.x;         // one float4 per thread (C/4 = 256)

    const float4 v = reinterpret_cast<const float4*>(x + (size_t)row * Cq)[i];
    float4 u = make_float4(0.f, 0.f, 0.f, 0.f);
    if (t > 0) u = reinterpret_cast<const float4*>(x + (size_t)(row - 1) * Cq)[i];

    float s  = v.x + v.y + v.z + v.w;
    float ss = v.x*v.x + v.y*v.y + v.z*v.z + v.w*v.w;
    float sp = u.x + u.y + u.z + u.w;
    float sq = u.x*u.x + u.y*u.y + u.z*u.z + u.w*u.w;
    bred4(s, ss, sp, sq);

    const float inv = 1.f / (float)Cq;
    const float mC = s * inv;
    const float rs = rsqrtf(ss * inv - mC * mC + 1e-5f);
    const float mP = sp * inv;
    const float rp = rsqrtf(sq * inv - mP * mP + 1e-5f);

    const float4 g4 = reinterpret_cast<const float4*>(g)[i];
    const float4 b4 = reinterpret_cast<const float4*>(be)[i];

    float xa[4], xx[4];
    const float* vv = &v.x; const float* uu = &u.x;
    const float* gg = &g4.x; const float* bb = &b4.x;
    #pragma unroll
    for (int j = 0; j < 4; j++) {
        xa[j] = (vv[j] - mC) * rs * gg[j] + bb[j];
        xx[j] = (t > 0) ? ((uu[j] - mP) * rp * gg[j] + bb[j]) : 0.f;
    }

    const size_t oi = (size_t)row * (Cq / 4) + i;
    {
        const float4 w4 = reinterpret_cast<const float4*>(m0)[i];
        const float* ww = &w4.x; float r[4];
        #pragma unroll
        for (int j = 0; j < 4; j++) r[j] = xa[j] * ww[j] + xx[j] * (1.f - ww[j]);
        __half2 h01 = __floats2half2_rn(r[0], r[1]);
        __half2 h23 = __floats2half2_rn(r[2], r[3]);
        uint2 o; o.x = *reinterpret_cast<uint32_t*>(&h01); o.y = *reinterpret_cast<uint32_t*>(&h23);
        reinterpret_cast<uint2*>(o0)[oi] = o;
    }
    {
        const float4 w4 = reinterpret_cast<const float4*>(m1)[i];
        const float* ww = &w4.x; float r[4];
        #pragma unroll
        for (int j = 0; j < 4; j++) r[j] = xa[j] * ww[j] + xx[j] * (1.f - ww[j]);
        __half2 h01 = __floats2half2_rn(r[0], r[1]);
        __half2 h23 = __floats2half2_rn(r[2], r[3]);
        uint2 o; o.x = *reinterpret_cast<uint32_t*>(&h01); o.y = *reinterpret_cast<uint32_t*>(&h23);
        reinterpret_cast<uint2*>(o1)[oi] = o;
    }
    if (NOUT == 3) {
        const float4 w4 = reinterpret_cast<const float4*>(m2)[i];
        const float* ww = &w4.x; float r[4];
        #pragma unroll
        for (int j = 0; j < 4; j++) r[j] = xa[j] * ww[j] + xx[j] * (1.f - ww[j]);
        __half2 h01 = __floats2half2_rn(r[0], r[1]);
        __half2 h23 = __floats2half2_rn(r[2], r[3]);
        uint2 o; o.x = *reinterpret_cast<uint32_t*>(&h01); o.y = *reinterpret_cast<uint32_t*>(&h23);
        reinterpret_cast<uint2*>(o2)[oi] = o;
    }
}

// ---------------- fp16 GEMM core (round-9 proven config) -------------------
// 128x128 tile, 128 threads, 4 warps @ 64x64, ldmatrix, 3-stage ring,
// prefetch distance 1, ONE __syncthreads per tile. 2 CTAs/SM.
// EPI: 0 none(f32) | 1 sigmoid(f32) | 2 relu^2 -> HALF out | 3 aux1+acc | 4 aux1+aux2*acc

__device__ __forceinline__ void fill_tile(uint32_t sbase, int stage,
    const __half* __restrict__ Ag, const __half* __restrict__ Wg, int K, int k0, int tid)
{
    const uint32_t sa = sbase + (uint32_t)stage * STGB;
    #pragma unroll
    for (int p = 0; p < 8; p++) {            // A: 128 rows x 8 chunks = 1024
        const int id  = tid + p * 128;
        const int row = id >> 3, c = id & 7;
        const uint32_t off = (uint32_t)(row * 128 + c * 16);
        cp16(sa + (off ^ ((off >> 3) & 0x70)), Ag + (size_t)row * K + k0 + c * 8);
    }
    const uint32_t sb = sa + ASTGB;
    #pragma unroll
    for (int p = 0; p < 8; p++) {            // B: 128 rows x 8 chunks = 1024
        const int id  = tid + p * 128;
        const int row = id >> 3, c = id & 7;
        const uint32_t off = (uint32_t)(row * 128 + c * 16);
        cp16(sb + (off ^ ((off >> 3) & 0x70)), Wg + (size_t)row * K + k0 + c * 8);
    }
}

template<int EPI>
__device__ __forceinline__ void epi_store(void* __restrict__ out, size_t idx,
    float c0, float c1, const float* __restrict__ a1, const float* __restrict__ a2)
{
    if (EPI == 2) {
        c0 = fmaxf(c0, 0.f); c0 *= c0;
        c1 = fmaxf(c1, 0.f); c1 *= c1;
        __half2 h = __floats2half2_rn(c0, c1);
        *reinterpret_cast<__half2*>((__half*)out + idx) = h;
        return;
    }
    if (EPI == 1) { c0 = 1.f / (1.f + __expf(-c0)); c1 = 1.f / (1.f + __expf(-c1)); }
    else if (EPI == 3) { c0 += a1[idx]; c1 += a1[idx + 1]; }
    else if (EPI == 4) { c0 = a1[idx] + a2[idx] * c0; c1 = a1[idx + 1] + a2[idx + 1] * c1; }
    float2 t; t.x = c0; t.y = c1;
    *reinterpret_cast<float2*>((float*)out + idx) = t;
}

template<int EPI>
__device__ __forceinline__ void gemm_body(
    const __half* __restrict__ A, const __half* __restrict__ W, void* __restrict__ out,
    const float* __restrict__ aux1, const float* __restrict__ aux2, int N, int K,
    uint32_t sbase, int bcol)
{
    const int tid  = threadIdx.x;
    const int lane = tid & 31;
    const int warp = tid >> 5;
    const int wm   = warp >> 1;   // 0..1 -> 64 rows each
    const int wn   = warp & 1;    // 0..1 -> 64 cols each

    const int brow = blockIdx.y * BM;
    const __half* Ag = A + (size_t)brow * K;
    const __half* Wg = W + (size_t)bcol * K;
    const int ntiles = K / BKK;

    // ldmatrix lane mapping (verified round-8 algebra)
    const int g = lane >> 3, r = lane & 7;
    const uint32_t colA = (uint32_t)((g >> 1) * 16);
    const uint32_t colB = (uint32_t)((g & 1) * 16);
    uint32_t arow128[4], axor[4];
    #pragma unroll
    for (int mt = 0; mt < 4; mt++) {
        const int row = wm * 64 + mt * 16 + (g & 1) * 8 + r;
        arow128[mt] = (uint32_t)(row * 128);
        axor[mt]    = (uint32_t)((row & 7) * 16);
    }
    uint32_t brow128[4], bxor[4];
    #pragma unroll
    for (int p = 0; p < 4; p++) {
        const int row = wn * 64 + p * 16 + (g >> 1) * 8 + r;
        brow128[p] = (uint32_t)(row * 128);
        bxor[p]    = (uint32_t)((row & 7) * 16);
    }

    // prologue: 1 tile in flight (prefetch distance 1)
    fill_tile(sbase, 0, Ag, Wg, K, 0, tid); cp_commit();

    float acc[4][8][4];
    #pragma unroll
    for (int mt = 0; mt < 4; mt++)
        #pragma unroll
        for (int nt = 0; nt < 8; nt++)
            #pragma unroll
            for (int q = 0; q < 4; q++) acc[mt][nt][q] = 0.f;

    for (int t = 0; t < ntiles; t++) {
        const int tp = t + 1;
        if (tp < ntiles) fill_tile(sbase, tp % STAGES, Ag, Wg, K, tp * BKK, tid);
        cp_commit();                       // unconditional (empty group on last iter)
        cp_wait<1>();                      // stage t complete
        __syncthreads();                   // the ONLY barrier per tile

        const uint32_t sA = sbase + (uint32_t)(t % STAGES) * STGB;
        const uint32_t sB = sA + ASTGB;

        #pragma unroll
        for (int ks = 0; ks < 4; ks++) {
            const uint32_t cb = (uint32_t)(ks * 32);
            uint32_t a[4][4], b[4][4];
            #pragma unroll
            for (int mt = 0; mt < 4; mt++)
                ldsm_x4(a[mt], sA + arow128[mt] + ((colA + cb) ^ axor[mt]));
            #pragma unroll
            for (int p = 0; p < 4; p++)
                ldsm_x4(b[p], sB + brow128[p] + ((colB + cb) ^ bxor[p]));
            #pragma unroll
            for (int mt = 0; mt < 4; mt++)
                #pragma unroll
                for (int nt = 0; nt < 8; nt++)
                    mma_f16(acc[mt][nt], a[mt], &b[nt >> 1][(nt & 1) * 2]);
        }
    }

    // epilogue straight from registers
    const int qrow = lane >> 2, qcol = lane & 3;
    #pragma unroll
    for (int mt = 0; mt < 4; mt++) {
        #pragma unroll
        for (int nt = 0; nt < 8; nt++) {
            const int row = brow + wm * 64 + mt * 16 + qrow;
            const int col = bcol + wn * 64 + nt * 8 + qcol * 2;
            const size_t i0 = (size_t)row * N + col;
            const size_t i1 = (size_t)(row + 8) * N + col;
            epi_store<EPI>(out, i0, acc[mt][nt][0], acc[mt][nt][1], aux1, aux2);
            epi_store<EPI>(out, i1, acc[mt][nt][2], acc[mt][nt][3], aux1, aux2);
        }
    }
}

template<int EPI>
__global__ __launch_bounds__(128, 2) void gemm_f16(
    const __half* __restrict__ A, const __half* __restrict__ W, void* __restrict__ out,
    const float* __restrict__ aux1, const float* __restrict__ aux2, int N, int K)
{
    extern __shared__ float dsm[];
    const uint32_t sbase = (smem_u32(dsm) + 1023u) & ~1023u;
    gemm_body<EPI>(A, W, out, aux1, aux2, N, K, sbase, blockIdx.x * BN);
}

// merged k, v, sr GEMMs: z=0 -> k (EPI0), z=1 -> v (EPI0), z=2 -> sigmoid(r) (EPI1)
__global__ __launch_bounds__(128, 2) void gemm_kvr(
    const __half* __restrict__ xk, const __half* __restrict__ xv, const __half* __restrict__ xr,
    const __half* __restrict__ wk, const __half* __restrict__ wv, const __half* __restrict__ wr,
    float* __restrict__ k, float* __restrict__ v, float* __restrict__ sr)
{
    extern __shared__ float dsm[];
    const uint32_t sbase = (smem_u32(dsm) + 1023u) & ~1023u;
    const int bcol = blockIdx.x * BN;
    if (blockIdx.z == 2)
        gemm_body<1>(xr, wr, sr, nullptr, nullptr, Cq, Cq, sbase, bcol);
    else if (blockIdx.z == 1)
        gemm_body<0>(xv, wv, v, nullptr, nullptr, Cq, Cq, sbase, bcol);
    else
        gemm_body<0>(xk, wk, k, nullptr, nullptr, Cq, Cq, sbase, bcol);
}

// merged Fk + Fr: blockIdx.x < 32 -> Fk tile (relu^2, half out, N=HID),
//                 blockIdx.x >= 32 -> Fr tile (sigmoid, N=C)
__global__ __launch_bounds__(128, 2) void gemm_fkr(
    const __half* __restrict__ fk, const __half* __restrict__ fr,
    const __half* __restrict__ wFk, const __half* __restrict__ wFr,
    __half* __restrict__ kk, float* __restrict__ sg)
{
    extern __shared__ float dsm[];
    const uint32_t sbase = (smem_u32(dsm) + 1023u) & ~1023u;
    if (blockIdx.x < (HIDq / BN))
        gemm_body<2>(fk, wFk, kk, nullptr, nullptr, HIDq, Cq, sbase, blockIdx.x * BN);
    else
        gemm_body<1>(fr, wFr, sg, nullptr, nullptr, Cq, Cq, sbase,
                     (blockIdx.x - HIDq / BN) * BN);
}

// ---------------- WKV chunked scan ------------------------------------------
__global__ __launch_bounds__(256) void wkv_phase_a(
    const float* __restrict__ k, const float* __restrict__ v,
    const float* __restrict__ td, float* __restrict__ Ca, float* __restrict__ Cb)
{
    const int gid = blockIdx.x * blockDim.x + threadIdx.x;   // < NCH*B*C
    const int c  = gid & (Cq - 1);
    const int r  = gid >> 10;
    const int b  = r & (Bq - 1);
    const int ch = r >> 3;
    const float w  = -expf(td[c]);
    const float dw = expf(w);
    const size_t base = ((size_t)(b * Tq + ch * LCH)) * Cq + c;
    float sa = 0.f, sb = 0.f;
    #pragma unroll 4
    for (int i = 0; i < LCH; i++) {
        const float kt = k[base + (size_t)i * Cq];
        const float vt = v[base + (size_t)i * Cq];
        const float ek = __expf(kt);
        sa = fmaf(dw, sa, ek * vt);
        sb = fmaf(dw, sb, ek);
    }
    Ca[gid] = sa; Cb[gid] = sb;
}

__global__ __launch_bounds__(256) void wkv_scan(
    const float* __restrict__ td,
    const float* __restrict__ Ca, const float* __restrict__ Cb,
    float* __restrict__ Sa, float* __restrict__ Sb)
{
    const int sid = blockIdx.x * blockDim.x + threadIdx.x;   // < B*C
    const int c = sid & (Cq - 1);
    const float w  = -expf(td[c]);
    const float dL = expf((float)LCH * w);
    float sa = 0.f, sb = 0.f;
    #pragma unroll
    for (int ch = 0; ch < NCH; ch++) {
        const int idx = ch * (Bq * Cq) + sid;
        Sa[idx] = sa; Sb[idx] = sb;
        sa = fmaf(dL, sa, Ca[idx]);
        sb = fmaf(dL, sb, Cb[idx]);
    }
}

__global__ __launch_bounds__(256) void wkv_phase_b(
    const float* __restrict__ k, const float* __restrict__ v, const float* __restrict__ sr,
    const float* __restrict__ td, const float* __restrict__ tf,
    const float* __restrict__ Sa, const float* __restrict__ Sb, __half* __restrict__ out)
{
    const int gid = blockIdx.x * blockDim.x + threadIdx.x;
    const int c  = gid & (Cq - 1);
    const int r  = gid >> 10;
    const int b  = r & (Bq - 1);
    const int ch = r >> 3;
    const float w  = -expf(td[c]);
    const float dw = expf(w);
    const float eu = expf(tf[c]);
    float a = Sa[gid], bb = Sb[gid];
    const size_t base = ((size_t)(b * Tq + ch * LCH)) * Cq + c;
    #pragma unroll 4
    for (int i = 0; i < LCH; i++) {
        const size_t off = base + (size_t)i * Cq;
        const float kt = k[off];
        const float vt = v[off];
        const float ek = __expf(kt);
        const float euk = eu * ek;
        const float y = (a + euk * vt) / (bb + euk);
        out[off] = __float2half_rn(sr[off] * y);   // feeds Wo GEMM only
        a  = fmaf(dw, a,  ek * vt);
        bb = fmaf(dw, bb, ek);
    }
}

// ---------------- launch -----------------------------------------------------
extern "C" void kernel_launch(void* const* d_in, const int* in_sizes, int n_in,
                              void* d_out, int out_size)
{
    const float* x     = (const float*)d_in[0];
    const float* ln1_g = (const float*)d_in[1];
    const float* ln1_b = (const float*)d_in[2];
    const float* ln2_g = (const float*)d_in[3];
    const float* ln2_b = (const float*)d_in[4];
    const float* td    = (const float*)d_in[5];
    const float* tf    = (const float*)d_in[6];
    const float* tmk   = (const float*)d_in[7];
    const float* tmv   = (const float*)d_in[8];
    const float* tmr   = (const float*)d_in[9];
    const float* Wk    = (const float*)d_in[10];
    const float* Wv    = (const float*)d_in[11];
    const float* Wr    = (const float*)d_in[12];
    const float* Wo    = (const float*)d_in[13];
    const float* fmk   = (const float*)d_in[14];
    const float* fmr   = (const float*)d_in[15];
    const float* Fk    = (const float*)d_in[16];
    const float* Fr    = (const float*)d_in[17];
    const float* Fv    = (const float*)d_in[18];
    float* out = (float*)d_out;

    __half *xk, *xv, *xr, *fk, *fr, *rw, *kk, *wh;
    float *k, *v, *sr, *x1, *sg, *Ca, *Cb, *Sa, *Sb;
    cudaGetSymbolAddress((void**)&xk, g_xk);
    cudaGetSymbolAddress((void**)&xv, g_xv);
    cudaGetSymbolAddress((void**)&xr, g_xr);
    cudaGetSymbolAddress((void**)&fk, g_fk);
    cudaGetSymbolAddress((void**)&fr, g_fr);
    cudaGetSymbolAddress((void**)&rw, g_rw);
    cudaGetSymbolAddress((void**)&kk, g_kk);
    cudaGetSymbolAddress((void**)&wh, g_wh);
    cudaGetSymbolAddress((void**)&k,  g_k);
    cudaGetSymbolAddress((void**)&v,  g_v);
    cudaGetSymbolAddress((void**)&sr, g_sr);
    cudaGetSymbolAddress((void**)&x1, g_x1);
    cudaGetSymbolAddress((void**)&sg, g_sg);
    cudaGetSymbolAddress((void**)&Ca, g_Ca);
    cudaGetSymbolAddress((void**)&Cb, g_Cb);
    cudaGetSymbolAddress((void**)&Sa, g_Sa);
    cudaGetSymbolAddress((void**)&Sb, g_Sb);

    const size_t CC = (size_t)Cq * Cq;          // 1M
    const size_t HC = (size_t)HIDq * Cq;        // 4M
    __half* hWk = wh;
    __half* hWv = wh + CC;
    __half* hWr = wh + 2 * CC;
    __half* hWo = wh + 3 * CC;
    __half* hFr = wh + 4 * CC;
    __half* hFk = wh + 5 * CC;
    __half* hFv = wh + 5 * CC + HC;

    cudaFuncSetAttribute(gemm_f16<3>, cudaFuncAttributeMaxDynamicSharedMemorySize, GEMM_SMEM);
    cudaFuncSetAttribute(gemm_f16<4>, cudaFuncAttributeMaxDynamicSharedMemorySize, GEMM_SMEM);
    cudaFuncSetAttribute(gemm_kvr,    cudaFuncAttributeMaxDynamicSharedMemorySize, GEMM_SMEM);
    cudaFuncSetAttribute(gemm_fkr,    cudaFuncAttributeMaxDynamicSharedMemorySize, GEMM_SMEM);

    // weight conversion
    w2h5<<<dim3((unsigned)(CC / 4 / 256), 5), 256>>>(Wk, Wv, Wr, Wo, Fr, wh);
    w2h2<<<dim3((unsigned)(HC / 4 / 256), 2), 256>>>(Fk, Fv, wh + 5 * CC);

    const dim3 gC  (Cq / BN,  Mq / BM);              // (8, 128)     N=1024
    const dim3 gC3 (Cq / BN,  Mq / BM, 3);           // (8, 128, 3)  k+v+sr merged
    const dim3 gFKR(HIDq / BN + Cq / BN, Mq / BM);   // (40, 128)    Fk+Fr merged

    // att branch
    ln_mix<3><<<Mq, 256>>>(x, ln1_g, ln1_b, tmk, tmv, tmr, xk, xv, xr);
    gemm_kvr<<<gC3, 128, GEMM_SMEM>>>(xk, xv, xr, hWk, hWv, hWr, k, v, sr);

    wkv_phase_a<<<(NCH * Bq * Cq) / 256, 256>>>(k, v, td, Ca, Cb);
    wkv_scan   <<<(Bq * Cq) / 256, 256>>>(td, Ca, Cb, Sa, Sb);
    wkv_phase_b<<<(NCH * Bq * Cq) / 256, 256>>>(k, v, sr, td, tf, Sa, Sb, rw);

    gemm_f16<3><<<gC, 128, GEMM_SMEM>>>(rw, hWo, x1, x, nullptr, Cq, Cq);

    // ffn branch
    ln_mix<2><<<Mq, 256>>>(x1, ln2_g, ln2_b, fmk, fmr, nullptr, fk, fr, nullptr);
    gemm_fkr<<<gFKR, 128, GEMM_SMEM>>>(fk, fr, hFk, hFr, kk, sg);
    gemm_f16<4><<<gC, 128, GEMM_SMEM>>>(kk, hFv, out, x1, sg, Cq, HIDq);
}

// round 12
// speedup vs baseline: 1.0592x; 1.0179x over previous
#include <cuda_runtime.h>
#include <cuda_fp16.h>
#include <cstdint>

// Problem dims (fixed)
#define Bq   8
#define Tq   2048
#define Cq   1024
#define HIDq 4096
#define Mq   (Bq*Tq)        // 16384 rows
#define NCH  32             // WKV chunks
#define LCH  (Tq/NCH)       // 64 steps per chunk

// GEMM tiling: CTA 128x128 (128 thr), warp 64x64, BK=64 fp16 (128B rows)
#define BM     128
#define BN     128
#define BKK    64
#define STAGES 3
#define ASTGB  (BM*128)              // 16384 bytes per A stage
#define BSTGB  (BN*128)              // 16384 bytes per B stage
#define STGB   (ASTGB + BSTGB)       // 32768 per stage
#define GEMM_SMEM (STAGES*STGB + 1024)   // 99328 -> 2 CTAs/SM

// ---------------- scratch (static device globals; no allocation) ----------
__device__ __half g_xk[(size_t)Mq*Cq];
__device__ __half g_xv[(size_t)Mq*Cq];
__device__ __half g_xr[(size_t)Mq*Cq];
__device__ __half g_fk[(size_t)Mq*Cq];
__device__ __half g_fr[(size_t)Mq*Cq];
__device__ __half g_rw[(size_t)Mq*Cq];
__device__ __half g_kk[(size_t)Mq*HIDq];
__device__ __half g_k [(size_t)Mq*Cq];
__device__ __half g_v [(size_t)Mq*Cq];
__device__ __half g_sr[(size_t)Mq*Cq];
__device__ float  g_x1[(size_t)Mq*Cq];
__device__ float  g_sg[(size_t)Mq*Cq];
__device__ float  g_Ca[(size_t)NCH*Bq*Cq];
__device__ float  g_Cb[(size_t)NCH*Bq*Cq];
__device__ float  g_Sa[(size_t)NCH*Bq*Cq];
__device__ float  g_Sb[(size_t)NCH*Bq*Cq];
// half weights: Wk,Wv,Wr,Wo,Fr (C*C each) then Fk,Fv (HID*C each)
__device__ __half g_wh[(size_t)5*Cq*Cq + (size_t)2*HIDq*Cq];

// ---------------- helpers --------------------------------------------------
__device__ __forceinline__ void mma_f16(float* c, const uint32_t* a, const uint32_t* b) {
    asm volatile(
        "mma.sync.aligned.m16n8k16.row.col.f32.f16.f16.f32 "
        "{%0,%1,%2,%3}, {%4,%5,%6,%7}, {%8,%9}, {%0,%1,%2,%3};"
        : "+f"(c[0]), "+f"(c[1]), "+f"(c[2]), "+f"(c[3])
        : "r"(a[0]), "r"(a[1]), "r"(a[2]), "r"(a[3]), "r"(b[0]), "r"(b[1]));
}
__device__ __forceinline__ void ldsm_x4(uint32_t* d, uint32_t addr) {
    asm volatile("ldmatrix.sync.aligned.m8n8.x4.shared.b16 {%0,%1,%2,%3}, [%4];"
        : "=r"(d[0]), "=r"(d[1]), "=r"(d[2]), "=r"(d[3]) : "r"(addr));
}

__device__ __forceinline__ uint32_t smem_u32(const void* p) {
    uint32_t a;
    asm("{ .reg .u64 t; cvta.to.shared.u64 t, %1; cvt.u32.u64 %0, t; }" : "=r"(a) : "l"(p));
    return a;
}
__device__ __forceinline__ void cp16(uint32_t dst, const void* src) {
    asm volatile("cp.async.cg.shared.global [%0], [%1], 16;" :: "r"(dst), "l"(src));
}
__device__ __forceinline__ void cp_commit() { asm volatile("cp.async.commit_group;"); }
template<int N> __device__ __forceinline__ void cp_wait() {
    asm volatile("cp.async.wait_group %0;" :: "n"(N));
}

// block-wide reduce of 4 values (256 threads)
__device__ __forceinline__ void bred4(float& a, float& b, float& c, float& d) {
    #pragma unroll
    for (int o = 16; o; o >>= 1) {
        a += __shfl_xor_sync(0xffffffffu, a, o);
        b += __shfl_xor_sync(0xffffffffu, b, o);
        c += __shfl_xor_sync(0xffffffffu, c, o);
        d += __shfl_xor_sync(0xffffffffu, d, o);
    }
    __shared__ float sm[8][4];
    int w = threadIdx.x >> 5, l = threadIdx.x & 31;
    if (l == 0) { sm[w][0] = a; sm[w][1] = b; sm[w][2] = c; sm[w][3] = d; }
    __syncthreads();
    a = b = c = d = 0.f;
    #pragma unroll
    for (int j = 0; j < 8; j++) { a += sm[j][0]; b += sm[j][1]; c += sm[j][2]; d += sm[j][3]; }
}

// ---------------- weight conversion fp32 -> fp16 ---------------------------
__global__ __launch_bounds__(256) void w2h5(
    const float* __restrict__ w0, const float* __restrict__ w1, const float* __restrict__ w2,
    const float* __restrict__ w3, const float* __restrict__ w4, __half* __restrict__ dst)
{
    const size_t CC = (size_t)Cq * Cq;
    const float* src = (blockIdx.y == 0) ? w0 : (blockIdx.y == 1) ? w1 :
                       (blockIdx.y == 2) ? w2 : (blockIdx.y == 3) ? w3 : w4;
    __half* d = dst + (size_t)blockIdx.y * CC;
    const int i = blockIdx.x * blockDim.x + threadIdx.x;   // < CC/4
    float4 v = reinterpret_cast<const float4*>(src)[i];
    __half2 h01 = __floats2half2_rn(v.x, v.y);
    __half2 h23 = __floats2half2_rn(v.z, v.w);
    uint2 u; u.x = *reinterpret_cast<uint32_t*>(&h01); u.y = *reinterpret_cast<uint32_t*>(&h23);
    reinterpret_cast<uint2*>(d)[i] = u;
}

__global__ __launch_bounds__(256) void w2h2(
    const float* __restrict__ w0, const float* __restrict__ w1, __half* __restrict__ dst)
{
    const size_t HC = (size_t)HIDq * Cq;
    const float* src = (blockIdx.y == 0) ? w0 : w1;
    __half* d = dst + (size_t)blockIdx.y * HC;
    const int i = blockIdx.x * blockDim.x + threadIdx.x;   // < HC/4
    float4 v = reinterpret_cast<const float4*>(src)[i];
    __half2 h01 = __floats2half2_rn(v.x, v.y);
    __half2 h23 = __floats2half2_rn(v.z, v.w);
    uint2 u; u.x = *reinterpret_cast<uint32_t*>(&h01); u.y = *reinterpret_cast<uint32_t*>(&h23);
    reinterpret_cast<uint2*>(d)[i] = u;
}

// ---------------- fused LayerNorm + time-shift + token-mix (half out) ------
template<int NOUT>
__global__ __launch_bounds__(256) void ln_mix(
    const float* __restrict__ x, const float* __restrict__ g, const float* __restrict__ be,
    const float* __restrict__ m0, const float* __restrict__ m1, const float* __restrict__ m2,
    __half* __restrict__ o0, __half* __restrict__ o1, __half* __restrict__ o2)
{
    const int row = blockIdx.x;          // b*T + t
    const int t   = row & (Tq - 1);
    const int i   = threadIdx.x;         // one float4 per thread (C/4 = 256)

    const float4 v = reinterpret_cast<const float4*>(x + (size_t)row * Cq)[i];
    float4 u = make_float4(0.f, 0.f, 0.f, 0.f);
    if (t > 0) u = reinterpret_cast<const float4*>(x + (size_t)(row - 1) * Cq)[i];

    float s  = v.x + v.y + v.z + v.w;
    float ss = v.x*v.x + v.y*v.y + v.z*v.z + v.w*v.w;
    float sp = u.x + u.y + u.z + u.w;
    float sq = u.x*u.x + u.y*u.y + u.z*u.z + u.w*u.w;
    bred4(s, ss, sp, sq);

    const float inv = 1.f / (float)Cq;
    const float mC = s * inv;
    const float rs = rsqrtf(ss * inv - mC * mC + 1e-5f);
    const float mP = sp * inv;
    const float rp = rsqrtf(sq * inv - mP * mP + 1e-5f);

    const float4 g4 = reinterpret_cast<const float4*>(g)[i];
    const float4 b4 = reinterpret_cast<const float4*>(be)[i];

    float xa[4], xx[4];
    const float* vv = &v.x; const float* uu = &u.x;
    const float* gg = &g4.x; const float* bb = &b4.x;
    #pragma unroll
    for (int j = 0; j < 4; j++) {
        xa[j] = (vv[j] - mC) * rs * gg[j] + bb[j];
        xx[j] = (t > 0) ? ((uu[j] - mP) * rp * gg[j] + bb[j]) : 0.f;
    }

    const size_t oi = (size_t)row * (Cq / 4) + i;
    {
        const float4 w4 = reinterpret_cast<const float4*>(m0)[i];
        const float* ww = &w4.x; float r[4];
        #pragma unroll
        for (int j = 0; j < 4; j++) r[j] = xa[j] * ww[j] + xx[j] * (1.f - ww[j]);
        __half2 h01 = __floats2half2_rn(r[0], r[1]);
        __half2 h23 = __floats2half2_rn(r[2], r[3]);
        uint2 o; o.x = *reinterpret_cast<uint32_t*>(&h01); o.y = *reinterpret_cast<uint32_t*>(&h23);
        reinterpret_cast<uint2*>(o0)[oi] = o;
    }
    {
        const float4 w4 = reinterpret_cast<const float4*>(m1)[i];
        const float* ww = &w4.x; float r[4];
        #pragma unroll
        for (int j = 0; j < 4; j++) r[j] = xa[j] * ww[j] + xx[j] * (1.f - ww[j]);
        __half2 h01 = __floats2half2_rn(r[0], r[1]);
        __half2 h23 = __floats2half2_rn(r[2], r[3]);
        uint2 o; o.x = *reinterpret_cast<uint32_t*>(&h01); o.y = *reinterpret_cast<uint32_t*>(&h23);
        reinterpret_cast<uint2*>(o1)[oi] = o;
    }
    if (NOUT == 3) {
        const float4 w4 = reinterpret_cast<const float4*>(m2)[i];
        const float* ww = &w4.x; float r[4];
        #pragma unroll
        for (int j = 0; j < 4; j++) r[j] = xa[j] * ww[j] + xx[j] * (1.f - ww[j]);
        __half2 h01 = __floats2half2_rn(r[0], r[1]);
        __half2 h23 = __floats2half2_rn(r[2], r[3]);
        uint2 o; o.x = *reinterpret_cast<uint32_t*>(&h01); o.y = *reinterpret_cast<uint32_t*>(&h23);
        reinterpret_cast<uint2*>(o2)[oi] = o;
    }
}

// ---------------- fp16 GEMM core (round-9 proven config) -------------------
// 128x128 tile, 128 threads, 4 warps @ 64x64, ldmatrix, 3-stage ring,
// prefetch distance 1, ONE __syncthreads per tile. 2 CTAs/SM.
// EPI: 0 none(f32) | 1 sigmoid(f32) | 2 relu^2->half | 3 aux1+acc(f32)
//      4 aux1+aux2*acc(f32) | 5 none->half | 6 sigmoid->half

__device__ __forceinline__ void fill_tile(uint32_t sbase, int stage,
    const __half* __restrict__ Ag, const __half* __restrict__ Wg, int K, int k0, int tid)
{
    const uint32_t sa = sbase + (uint32_t)stage * STGB;
    #pragma unroll
    for (int p = 0; p < 8; p++) {            // A: 128 rows x 8 chunks = 1024
        const int id  = tid + p * 128;
        const int row = id >> 3, c = id & 7;
        const uint32_t off = (uint32_t)(row * 128 + c * 16);
        cp16(sa + (off ^ ((off >> 3) & 0x70)), Ag + (size_t)row * K + k0 + c * 8);
    }
    const uint32_t sb = sa + ASTGB;
    #pragma unroll
    for (int p = 0; p < 8; p++) {            // B: 128 rows x 8 chunks = 1024
        const int id  = tid + p * 128;
        const int row = id >> 3, c = id & 7;
        const uint32_t off = (uint32_t)(row * 128 + c * 16);
        cp16(sb + (off ^ ((off >> 3) & 0x70)), Wg + (size_t)row * K + k0 + c * 8);
    }
}

template<int EPI>
__device__ __forceinline__ void epi_store(void* __restrict__ out, size_t idx,
    float c0, float c1, const float* __restrict__ a1, const float* __restrict__ a2)
{
    if (EPI == 2 || EPI == 5 || EPI == 6) {
        if (EPI == 2) {
            c0 = fmaxf(c0, 0.f); c0 *= c0;
            c1 = fmaxf(c1, 0.f); c1 *= c1;
        } else if (EPI == 6) {
            c0 = 1.f / (1.f + __expf(-c0));
            c1 = 1.f / (1.f + __expf(-c1));
        }
        __half2 h = __floats2half2_rn(c0, c1);
        *reinterpret_cast<__half2*>((__half*)out + idx) = h;
        return;
    }
    if (EPI == 1) { c0 = 1.f / (1.f + __expf(-c0)); c1 = 1.f / (1.f + __expf(-c1)); }
    else if (EPI == 3) { c0 += a1[idx]; c1 += a1[idx + 1]; }
    else if (EPI == 4) { c0 = a1[idx] + a2[idx] * c0; c1 = a1[idx + 1] + a2[idx + 1] * c1; }
    float2 t; t.x = c0; t.y = c1;
    *reinterpret_cast<float2*>((float*)out + idx) = t;
}

template<int EPI>
__device__ __forceinline__ void gemm_body(
    const __half* __restrict__ A, const __half* __restrict__ W, void* __restrict__ out,
    const float* __restrict__ aux1, const float* __restrict__ aux2, int N, int K,
    uint32_t sbase, int bcol)
{
    const int tid  = threadIdx.x;
    const int lane = tid & 31;
    const int warp = tid >> 5;
    const int wm   = warp >> 1;   // 0..1 -> 64 rows each
    const int wn   = warp & 1;    // 0..1 -> 64 cols each

    const int brow = blockIdx.y * BM;
    const __half* Ag = A + (size_t)brow * K;
    const __half* Wg = W + (size_t)bcol * K;
    const int ntiles = K / BKK;

    // ldmatrix lane mapping (verified round-8 algebra)
    const int g = lane >> 3, r = lane & 7;
    const uint32_t colA = (uint32_t)((g >> 1) * 16);
    const uint32_t colB = (uint32_t)((g & 1) * 16);
    uint32_t arow128[4], axor[4];
    #pragma unroll
    for (int mt = 0; mt < 4; mt++) {
        const int row = wm * 64 + mt * 16 + (g & 1) * 8 + r;
        arow128[mt] = (uint32_t)(row * 128);
        axor[mt]    = (uint32_t)((row & 7) * 16);
    }
    uint32_t brow128[4], bxor[4];
    #pragma unroll
    for (int p = 0; p < 4; p++) {
        const int row = wn * 64 + p * 16 + (g >> 1) * 8 + r;
        brow128[p] = (uint32_t)(row * 128);
        bxor[p]    = (uint32_t)((row & 7) * 16);
    }

    // prologue: 1 tile in flight (prefetch distance 1)
    fill_tile(sbase, 0, Ag, Wg, K, 0, tid); cp_commit();

    float acc[4][8][4];
    #pragma unroll
    for (int mt = 0; mt < 4; mt++)
        #pragma unroll
        for (int nt = 0; nt < 8; nt++)
            #pragma unroll
            for (int q = 0; q < 4; q++) acc[mt][nt][q] = 0.f;

    for (int t = 0; t < ntiles; t++) {
        const int tp = t + 1;
        if (tp < ntiles) fill_tile(sbase, tp % STAGES, Ag, Wg, K, tp * BKK, tid);
        cp_commit();                       // unconditional (empty group on last iter)
        cp_wait<1>();                      // stage t complete
        __syncthreads();                   // the ONLY barrier per tile

        const uint32_t sA = sbase + (uint32_t)(t % STAGES) * STGB;
        const uint32_t sB = sA + ASTGB;

        #pragma unroll
        for (int ks = 0; ks < 4; ks++) {
            const uint32_t cb = (uint32_t)(ks * 32);
            uint32_t a[4][4], b[4][4];
            #pragma unroll
            for (int mt = 0; mt < 4; mt++)
                ldsm_x4(a[mt], sA + arow128[mt] + ((colA + cb) ^ axor[mt]));
            #pragma unroll
            for (int p = 0; p < 4; p++)
                ldsm_x4(b[p], sB + brow128[p] + ((colB + cb) ^ bxor[p]));
            #pragma unroll
            for (int mt = 0; mt < 4; mt++)
                #pragma unroll
                for (int nt = 0; nt < 8; nt++)
                    mma_f16(acc[mt][nt], a[mt], &b[nt >> 1][(nt & 1) * 2]);
        }
    }

    // epilogue straight from registers
    const int qrow = lane >> 2, qcol = lane & 3;
    #pragma unroll
    for (int mt = 0; mt < 4; mt++) {
        #pragma unroll
        for (int nt = 0; nt < 8; nt++) {
            const int row = brow + wm * 64 + mt * 16 + qrow;
            const int col = bcol + wn * 64 + nt * 8 + qcol * 2;
            const size_t i0 = (size_t)row * N + col;
            const size_t i1 = (size_t)(row + 8) * N + col;
            epi_store<EPI>(out, i0, acc[mt][nt][0], acc[mt][nt][1], aux1, aux2);
            epi_store<EPI>(out, i1, acc[mt][nt][2], acc[mt][nt][3], aux1, aux2);
        }
    }
}

template<int EPI>
__global__ __launch_bounds__(128, 2) void gemm_f16(
    const __half* __restrict__ A, const __half* __restrict__ W, void* __restrict__ out,
    const float* __restrict__ aux1, const float* __restrict__ aux2, int N, int K)
{
    extern __shared__ float dsm[];
    const uint32_t sbase = (smem_u32(dsm) + 1023u) & ~1023u;
    gemm_body<EPI>(A, W, out, aux1, aux2, N, K, sbase, blockIdx.x * BN);
}

// merged k, v, sr GEMMs (half outputs): z=0 -> k, z=1 -> v, z=2 -> sigmoid(r)
__global__ __launch_bounds__(128, 2) void gemm_kvr(
    const __half* __restrict__ xk, const __half* __restrict__ xv, const __half* __restrict__ xr,
    const __half* __restrict__ wk, const __half* __restrict__ wv, const __half* __restrict__ wr,
    __half* __restrict__ k, __half* __restrict__ v, __half* __restrict__ sr)
{
    extern __shared__ float dsm[];
    const uint32_t sbase = (smem_u32(dsm) + 1023u) & ~1023u;
    const int bcol = blockIdx.x * BN;
    if (blockIdx.z == 2)
        gemm_body<6>(xr, wr, sr, nullptr, nullptr, Cq, Cq, sbase, bcol);
    else if (blockIdx.z == 1)
        gemm_body<5>(xv, wv, v, nullptr, nullptr, Cq, Cq, sbase, bcol);
    else
        gemm_body<5>(xk, wk, k, nullptr, nullptr, Cq, Cq, sbase, bcol);
}

// merged Fk + Fr: blockIdx.x < 32 -> Fk tile (relu^2, half out, N=HID),
//                 blockIdx.x >= 32 -> Fr tile (sigmoid, N=C)
__global__ __launch_bounds__(128, 2) void gemm_fkr(
    const __half* __restrict__ fk, const __half* __restrict__ fr,
    const __half* __restrict__ wFk, const __half* __restrict__ wFr,
    __half* __restrict__ kk, float* __restrict__ sg)
{
    extern __shared__ float dsm[];
    const uint32_t sbase = (smem_u32(dsm) + 1023u) & ~1023u;
    if (blockIdx.x < (HIDq / BN))
        gemm_body<2>(fk, wFk, kk, nullptr, nullptr, HIDq, Cq, sbase, blockIdx.x * BN);
    else
        gemm_body<1>(fr, wFr, sg, nullptr, nullptr, Cq, Cq, sbase,
                     (blockIdx.x - HIDq / BN) * BN);
}

// ---------------- WKV chunked scan (half k/v/sr, half2 vectorized) ---------
__global__ __launch_bounds__(256) void wkv_phase_a(
    const __half* __restrict__ k, const __half* __restrict__ v,
    const float* __restrict__ td, float* __restrict__ Ca, float* __restrict__ Cb)
{
    const int gid = blockIdx.x * blockDim.x + threadIdx.x;   // < NCH*B*C/2
    const int c2 = gid & (Cq / 2 - 1);
    const int r  = gid >> 9;
    const int b  = r & (Bq - 1);
    const int ch = r >> 3;
    const float2 tdv = *reinterpret_cast<const float2*>(td + c2 * 2);
    const float dw0 = expf(-expf(tdv.x));
    const float dw1 = expf(-expf(tdv.y));
    const size_t base = ((size_t)(b * Tq + ch * LCH)) * Cq + c2 * 2;
    float sa0 = 0.f, sa1 = 0.f, sb0 = 0.f, sb1 = 0.f;
    #pragma unroll 4
    for (int i = 0; i < LCH; i++) {
        const float2 kf = __half22float2(*reinterpret_cast<const __half2*>(k + base + (size_t)i * Cq));
        const float2 vf = __half22float2(*reinterpret_cast<const __half2*>(v + base + (size_t)i * Cq));
        const float e0 = __expf(kf.x), e1 = __expf(kf.y);
        sa0 = fmaf(dw0, sa0, e0 * vf.x); sb0 = fmaf(dw0, sb0, e0);
        sa1 = fmaf(dw1, sa1, e1 * vf.y); sb1 = fmaf(dw1, sb1, e1);
    }
    const int idx = (r << 10) + c2 * 2;
    float2 oa; oa.x = sa0; oa.y = sa1;
    float2 ob; ob.x = sb0; ob.y = sb1;
    *reinterpret_cast<float2*>(Ca + idx) = oa;
    *reinterpret_cast<float2*>(Cb + idx) = ob;
}

__global__ __launch_bounds__(256) void wkv_scan(
    const float* __restrict__ td,
    const float* __restrict__ Ca, const float* __restrict__ Cb,
    float* __restrict__ Sa, float* __restrict__ Sb)
{
    const int sid = blockIdx.x * blockDim.x + threadIdx.x;   // < B*C
    const int c = sid & (Cq - 1);
    const float w  = -expf(td[c]);
    const float dL = expf((float)LCH * w);
    float sa = 0.f, sb = 0.f;
    #pragma unroll
    for (int ch = 0; ch < NCH; ch++) {
        const int idx = ch * (Bq * Cq) + sid;
        Sa[idx] = sa; Sb[idx] = sb;
        sa = fmaf(dL, sa, Ca[idx]);
        sb = fmaf(dL, sb, Cb[idx]);
    }
}

__global__ __launch_bounds__(256) void wkv_phase_b(
    const __half* __restrict__ k, const __half* __restrict__ v, const __half* __restrict__ sr,
    const float* __restrict__ td, const float* __restrict__ tf,
    const float* __restrict__ Sa, const float* __restrict__ Sb, __half* __restrict__ out)
{
    const int gid = blockIdx.x * blockDim.x + threadIdx.x;   // < NCH*B*C/2
    const int c2 = gid & (Cq / 2 - 1);
    const int r  = gid >> 9;
    const int b  = r & (Bq - 1);
    const int ch = r >> 3;
    const float2 tdv = *reinterpret_cast<const float2*>(td + c2 * 2);
    const float2 tfv = *reinterpret_cast<const float2*>(tf + c2 * 2);
    const float dw0 = expf(-expf(tdv.x));
    const float dw1 = expf(-expf(tdv.y));
    const float eu0 = expf(tfv.x), eu1 = expf(tfv.y);
    const int idx = (r << 10) + c2 * 2;
    float2 af = *reinterpret_cast<const float2*>(Sa + idx);
    float2 bf = *reinterpret_cast<const float2*>(Sb + idx);
    const size_t base = ((size_t)(b * Tq + ch * LCH)) * Cq + c2 * 2;
    #pragma unroll 4
    for (int i = 0; i < LCH; i++) {
        const size_t off = base + (size_t)i * Cq;
        const float2 kf = __half22float2(*reinterpret_cast<const __half2*>(k + off));
        const float2 vf = __half22float2(*reinterpret_cast<const __half2*>(v + off));
        const float2 sf = __half22float2(*reinterpret_cast<const __half2*>(sr + off));
        const float e0 = __expf(kf.x), e1 = __expf(kf.y);
        const float euk0 = eu0 * e0, euk1 = eu1 * e1;
        const float y0 = (af.x + euk0 * vf.x) / (bf.x + euk0);
        const float y1 = (af.y + euk1 * vf.y) / (bf.y + euk1);
        *reinterpret_cast<__half2*>(out + off) = __floats2half2_rn(sf.x * y0, sf.y * y1);
        af.x = fmaf(dw0, af.x, e0 * vf.x); bf.x = fmaf(dw0, bf.x, e0);
        af.y = fmaf(dw1, af.y, e1 * vf.y); bf.y = fmaf(dw1, bf.y, e1);
    }
}

// ---------------- launch -----------------------------------------------------
extern "C" void kernel_launch(void* const* d_in, const int* in_sizes, int n_in,
                              void* d_out, int out_size)
{
    const float* x     = (const float*)d_in[0];
    const float* ln1_g = (const float*)d_in[1];
    const float* ln1_b = (const float*)d_in[2];
    const float* ln2_g = (const float*)d_in[3];
    const float* ln2_b = (const float*)d_in[4];
    const float* td    = (const float*)d_in[5];
    const float* tf    = (const float*)d_in[6];
    const float* tmk   = (const float*)d_in[7];
    const float* tmv   = (const float*)d_in[8];
    const float* tmr   = (const float*)d_in[9];
    const float* Wk    = (const float*)d_in[10];
    const float* Wv    = (const float*)d_in[11];
    const float* Wr    = (const float*)d_in[12];
    const float* Wo    = (const float*)d_in[13];
    const float* fmk   = (const float*)d_in[14];
    const float* fmr   = (const float*)d_in[15];
    const float* Fk    = (const float*)d_in[16];
    const float* Fr    = (const float*)d_in[17];
    const float* Fv    = (const float*)d_in[18];
    float* out = (float*)d_out;

    __half *xk, *xv, *xr, *fk, *fr, *rw, *kk, *wh, *k, *v, *sr;
    float *x1, *sg, *Ca, *Cb, *Sa, *Sb;
    cudaGetSymbolAddress((void**)&xk, g_xk);
    cudaGetSymbolAddress((void**)&xv, g_xv);
    cudaGetSymbolAddress((void**)&xr, g_xr);
    cudaGetSymbolAddress((void**)&fk, g_fk);
    cudaGetSymbolAddress((void**)&fr, g_fr);
    cudaGetSymbolAddress((void**)&rw, g_rw);
    cudaGetSymbolAddress((void**)&kk, g_kk);
    cudaGetSymbolAddress((void**)&wh, g_wh);
    cudaGetSymbolAddress((void**)&k,  g_k);
    cudaGetSymbolAddress((void**)&v,  g_v);
    cudaGetSymbolAddress((void**)&sr, g_sr);
    cudaGetSymbolAddress((void**)&x1, g_x1);
    cudaGetSymbolAddress((void**)&sg, g_sg);
    cudaGetSymbolAddress((void**)&Ca, g_Ca);
    cudaGetSymbolAddress((void**)&Cb, g_Cb);
    cudaGetSymbolAddress((void**)&Sa, g_Sa);
    cudaGetSymbolAddress((void**)&Sb, g_Sb);

    const size_t CC = (size_t)Cq * Cq;          // 1M
    const size_t HC = (size_t)HIDq * Cq;        // 4M
    __half* hWk = wh;
    __half* hWv = wh + CC;
    __half* hWr = wh + 2 * CC;
    __half* hWo = wh + 3 * CC;
    __half* hFr = wh + 4 * CC;
    __half* hFk = wh + 5 * CC;
    __half* hFv = wh + 5 * CC + HC;

    cudaFuncSetAttribute(gemm_f16<3>, cudaFuncAttributeMaxDynamicSharedMemorySize, GEMM_SMEM);
    cudaFuncSetAttribute(gemm_f16<4>, cudaFuncAttributeMaxDynamicSharedMemorySize, GEMM_SMEM);
    cudaFuncSetAttribute(gemm_kvr,    cudaFuncAttributeMaxDynamicSharedMemorySize, GEMM_SMEM);
    cudaFuncSetAttribute(gemm_fkr,    cudaFuncAttributeMaxDynamicSharedMemorySize, GEMM_SMEM);

    // weight conversion
    w2h5<<<dim3((unsigned)(CC / 4 / 256), 5), 256>>>(Wk, Wv, Wr, Wo, Fr, wh);
    w2h2<<<dim3((unsigned)(HC / 4 / 256), 2), 256>>>(Fk, Fv, wh + 5 * CC);

    const dim3 gC  (Cq / BN,  Mq / BM);              // (8, 128)     N=1024
    const dim3 gC3 (Cq / BN,  Mq / BM, 3);           // (8, 128, 3)  k+v+sr merged
    const dim3 gFKR(HIDq / BN + Cq / BN, Mq / BM);   // (40, 128)    Fk+Fr merged

    // att branch
    ln_mix<3><<<Mq, 256>>>(x, ln1_g, ln1_b, tmk, tmv, tmr, xk, xv, xr);
    gemm_kvr<<<gC3, 128, GEMM_SMEM>>>(xk, xv, xr, hWk, hWv, hWr, k, v, sr);

    wkv_phase_a<<<(NCH * Bq * Cq / 2) / 256, 256>>>(k, v, td, Ca, Cb);
    wkv_scan   <<<(Bq * Cq) / 256, 256>>>(td, Ca, Cb, Sa, Sb);
    wkv_phase_b<<<(NCH * Bq * Cq / 2) / 256, 256>>>(k, v, sr, td, tf, Sa, Sb, rw);

    gemm_f16<3><<<gC, 128, GEMM_SMEM>>>(rw, hWo, x1, x, nullptr, Cq, Cq);

    // ffn branch
    ln_mix<2><<<Mq, 256>>>(x1, ln2_g, ln2_b, fmk, fmr, nullptr, fk, fr, nullptr);
    gemm_fkr<<<gFKR, 128, GEMM_SMEM>>>(fk, fr, hFk, hFr, kk, sg);
    gemm_f16<4><<<gC, 128, GEMM_SMEM>>>(kk, hFv, out, x1, sg, Cq, HIDq);
}